// round 3
// baseline (speedup 1.0000x reference)
#include <cuda_runtime.h>
#include <cuda_bf16.h>
#include <math.h>
#include <stdint.h>

// Problem constants
#define B_    64
#define T_    2048
#define ENC_  512
#define DEC_  1024
#define HID_  256
#define KCONV 31
#define PADC  15

// GEMM tiling: CTA = 64 (bt) x 256 (h), K-chunk 32, double-buffered
#define TM 64
#define KC2 32
#define LDA2 40               // 32 + 8 pad (80B row = 16B-aligned, conflict-free)
#define STAGE_ELEMS (TM*LDA2*2 + HID_*LDA2*2)   // Ahi,Alo,Whi,Wlo = 25600
#define SMEM2 (2 * STAGE_ELEMS * 2)             // 102400 bytes

// ---------------- device scratch ----------------
__device__ __nv_bfloat16 g_Whi[HID_ * ENC_];
__device__ __nv_bfloat16 g_Wlo[HID_ * ENC_];
__device__ __nv_bfloat16 g_F[HID_ * 32];        // fused conv filter, col 31 = 0
__device__ float g_dec[B_ * HID_];              // dec projection + b_enc
__device__ float g_energy[B_ * T_];
__device__ float g_part[B_ * 16 * ENC_];        // att_c partials (16 t-slices)

// ---------------- cp.async helpers ----------------
__device__ __forceinline__ void cp16(void* dst, const void* src) {
    uint32_t d = (uint32_t)__cvta_generic_to_shared(dst);
    asm volatile("cp.async.cg.shared.global [%0], [%1], 16;\n" :: "r"(d), "l"(src));
}
#define CP_COMMIT() asm volatile("cp.async.commit_group;\n" ::: "memory")
#define CP_WAIT0()  asm volatile("cp.async.wait_group 0;\n" ::: "memory")

// ---------------- merged prep kernel ----------------
// blocks [0,512): W_enc -> hi/lo bf16
// blocks [512,544): fused conv filter F = W_att * conv_w
// blocks [544,2592): dec projection, one warp per output element
__global__ void prep_all(const float* __restrict__ W_enc,
                         const float* __restrict__ W_att,
                         const float* __restrict__ conv_w,
                         const float* __restrict__ dec_state,
                         const float* __restrict__ W_dec,
                         const float* __restrict__ b_enc) {
    int bx = blockIdx.x, tid = threadIdx.x;
    if (bx < 512) {
        int i = bx * 256 + tid;
        float x = W_enc[i];
        __nv_bfloat16 h = __float2bfloat16(x);
        g_Whi[i] = h;
        g_Wlo[i] = __float2bfloat16(x - __bfloat162float(h));
    } else if (bx < 544) {
        int i = (bx - 512) * 256 + tid;
        int h = i >> 5, k = i & 31;
        float s = 0.f;
        if (k < KCONV) {
            #pragma unroll
            for (int c = 0; c < 32; c++) s += W_att[h * 32 + c] * conv_w[c * KCONV + k];
        }
        g_F[i] = __float2bfloat16(s);
    } else {
        int wid_g = (bx - 544) * 8 + (tid >> 5);   // 0..16383
        int lane = tid & 31;
        int b = wid_g >> 8, h = wid_g & 255;
        const float4* d = (const float4*)(dec_state + (size_t)b * DEC_);
        const float4* w = (const float4*)(W_dec + (size_t)h * DEC_);
        float s = 0.f;
        #pragma unroll
        for (int it = 0; it < 8; it++) {
            float4 dv = d[lane + it * 32];
            float4 wv = w[lane + it * 32];
            s += dv.x * wv.x + dv.y * wv.y + dv.z * wv.z + dv.w * wv.w;
        }
        #pragma unroll
        for (int off = 16; off > 0; off >>= 1) s += __shfl_xor_sync(0xffffffffu, s, off);
        if (lane == 0) g_dec[wid_g] = s + b_enc[h];
    }
}

// ---------------- mma helpers ----------------
__device__ __forceinline__ void mma_bf16(float& c0, float& c1, float& c2, float& c3,
                                         uint32_t a0, uint32_t a1, uint32_t a2, uint32_t a3,
                                         uint32_t b0, uint32_t b1) {
    asm volatile(
        "mma.sync.aligned.m16n8k16.row.col.f32.bf16.bf16.f32 "
        "{%0,%1,%2,%3}, {%4,%5,%6,%7}, {%8,%9}, {%0,%1,%2,%3};"
        : "+f"(c0), "+f"(c1), "+f"(c2), "+f"(c3)
        : "r"(a0), "r"(a1), "r"(a2), "r"(a3), "r"(b0), "r"(b1));
}

// A: [64][LDA2] bf16, W: [256][LDA2] bf16. Warp wn owns n-cols [wn*32, wn*32+32).
__device__ __forceinline__ void mma_pass(const __nv_bfloat16* __restrict__ As,
                                         const __nv_bfloat16* __restrict__ Ws,
                                         int ksteps,
                                         float (&acc)[4][4][4],
                                         int wn, int lane) {
    int g  = lane >> 2;
    int tq = lane & 3;
    for (int ks = 0; ks < ksteps; ks++) {
        int kb = ks * 16 + tq * 2;
        uint32_t af[4][4];
        #pragma unroll
        for (int mi = 0; mi < 4; mi++) {
            const __nv_bfloat16* ap = As + (mi * 16 + g) * LDA2 + kb;
            af[mi][0] = *(const uint32_t*)(ap);
            af[mi][1] = *(const uint32_t*)(ap + 8 * LDA2);
            af[mi][2] = *(const uint32_t*)(ap + 8);
            af[mi][3] = *(const uint32_t*)(ap + 8 * LDA2 + 8);
        }
        #pragma unroll
        for (int ni = 0; ni < 4; ni++) {
            const __nv_bfloat16* bp = Ws + (wn * 32 + ni * 8 + g) * LDA2 + kb;
            uint32_t b0 = *(const uint32_t*)(bp);
            uint32_t b1 = *(const uint32_t*)(bp + 8);
            #pragma unroll
            for (int mi = 0; mi < 4; mi++) {
                mma_bf16(acc[mi][ni][0], acc[mi][ni][1], acc[mi][ni][2], acc[mi][ni][3],
                         af[mi][0], af[mi][1], af[mi][2], af[mi][3], b0, b1);
            }
        }
    }
}

// ---------------- energy kernel (pipelined, double-buffered) ----------------
__global__ void __launch_bounds__(256, 2)
energy_kernel(const float* __restrict__ enc,
              const float* __restrict__ prev,
              const float* __restrict__ w_w) {
    extern __shared__ char smraw[];
    __nv_bfloat16* stage[2];
    stage[0] = (__nv_bfloat16*)smraw;
    stage[1] = stage[0] + STAGE_ELEMS;
    // per-stage sub-pointers: Ahi, Alo, Whi, Wlo
    float* red = (float*)smraw;

    const int tid  = threadIdx.x;
    const int lane = tid & 31;
    const int wn   = tid >> 5;   // 0..7, n-slice

    const int m0 = blockIdx.x * TM;
    const int b  = m0 >> 11;
    const int t0 = m0 & (T_ - 1);

    const int arow = tid >> 2;   // 0..63
    const int aq   = tid & 3;    // col group of 8

    float acc[4][4][4];
    #pragma unroll
    for (int mi = 0; mi < 4; mi++)
        #pragma unroll
        for (int ni = 0; ni < 4; ni++)
            #pragma unroll
            for (int r = 0; r < 4; r++) acc[mi][ni][r] = 0.f;

    const float* encb = enc + ((size_t)b * T_ + t0) * ENC_;
    const float* arow_ptr = encb + (size_t)arow * ENC_ + aq * 8;

    // ---- stage buffer helpers (computed inline) ----
    // Ahi = stage[s]; Alo = +TM*LDA2; Whi = +2*TM*LDA2; Wlo = +2*TM*LDA2+HID_*LDA2
    #define AHI(s) (stage[s])
    #define ALO(s) (stage[s] + TM * LDA2)
    #define WHI(s) (stage[s] + 2 * TM * LDA2)
    #define WLO(s) (stage[s] + 2 * TM * LDA2 + HID_ * LDA2)

    // W preload via cp.async: thread = one of 256 rows, 4x16B per matrix
    #define LOAD_W(s, kc) do {                                                  \
        const __nv_bfloat16* srh = g_Whi + (size_t)tid * ENC_ + (kc);           \
        const __nv_bfloat16* srl = g_Wlo + (size_t)tid * ENC_ + (kc);           \
        __nv_bfloat16* dh = WHI(s) + tid * LDA2;                                \
        __nv_bfloat16* dl = WLO(s) + tid * LDA2;                                \
        _Pragma("unroll")                                                       \
        for (int j = 0; j < 4; j++) {                                           \
            cp16(dh + j * 8, srh + j * 8);                                      \
            cp16(dl + j * 8, srl + j * 8);                                      \
        }                                                                       \
    } while (0)

    #define STORE_A(s, v0, v1) do {                                             \
        __nv_bfloat16* dh = AHI(s) + arow * LDA2 + aq * 8;                      \
        __nv_bfloat16* dl = ALO(s) + arow * LDA2 + aq * 8;                      \
        float fv[8] = {v0.x, v0.y, v0.z, v0.w, v1.x, v1.y, v1.z, v1.w};         \
        _Pragma("unroll")                                                       \
        for (int j = 0; j < 4; j++) {                                           \
            __nv_bfloat16 h0 = __float2bfloat16(fv[2*j]);                       \
            __nv_bfloat16 h1 = __float2bfloat16(fv[2*j+1]);                     \
            __nv_bfloat162 hp; hp.x = h0; hp.y = h1;                            \
            __nv_bfloat162 lp = __floats2bfloat162_rn(                          \
                fv[2*j]   - __bfloat162float(h0),                               \
                fv[2*j+1] - __bfloat162float(h1));                              \
            *(__nv_bfloat162*)(dh + 2*j) = hp;                                  \
            *(__nv_bfloat162*)(dl + 2*j) = lp;                                  \
        }                                                                       \
    } while (0)

    // ---- prologue: chunk 0 ----
    float4 va, vb;
    LOAD_W(0, 0);
    CP_COMMIT();
    va = *(const float4*)(arow_ptr);
    vb = *(const float4*)(arow_ptr + 4);
    STORE_A(0, va, vb);
    CP_WAIT0();
    __syncthreads();

    // ---- main loop: 16 chunks of KC2=32 ----
    for (int c = 0; c < 16; c++) {
        int cur = c & 1, nxt = cur ^ 1;
        if (c < 15) {
            LOAD_W(nxt, (c + 1) * KC2);
            CP_COMMIT();
            va = *(const float4*)(arow_ptr + (c + 1) * KC2);
            vb = *(const float4*)(arow_ptr + (c + 1) * KC2 + 4);
        }
        mma_pass(AHI(cur), WHI(cur), 2, acc, wn, lane);   // hi*hi
        mma_pass(ALO(cur), WHI(cur), 2, acc, wn, lane);   // lo*hi
        mma_pass(AHI(cur), WLO(cur), 2, acc, wn, lane);   // hi*lo
        if (c < 15) {
            STORE_A(nxt, va, vb);
            CP_WAIT0();
        }
        __syncthreads();
    }

    // ---- conv chunk: shifted prev_att_w (64x32) against fused filter F (256x32) ----
    {
        // prev tile into AHI(0)
        __nv_bfloat16* da = AHI(0) + arow * LDA2 + aq * 8;
        #pragma unroll
        for (int j = 0; j < 8; j++) {
            int k = aq * 8 + j;
            int t = t0 + arow - PADC + k;
            float v = (t >= 0 && t < T_) ? prev[b * T_ + t] : 0.f;  // k==31 hits F==0
            da[j] = __float2bfloat16(v);
        }
        // F into WHI(0)
        const uint4* sf = (const uint4*)(g_F + tid * 32);
        uint4* df = (uint4*)(WHI(0) + tid * LDA2);
        #pragma unroll
        for (int j = 0; j < 4; j++) df[j] = sf[j];
    }
    __syncthreads();
    mma_pass(AHI(0), WHI(0), 2, acc, wn, lane);
    __syncthreads();

    // ---- epilogue: energy[row] = sum_h w_w[h] * tanh(acc + dec) ----
    float wv[8], dv[8];
    {
        int cbase = wn * 32 + (lane & 3) * 2;
        #pragma unroll
        for (int ni = 0; ni < 4; ni++) {
            int n = cbase + ni * 8;
            wv[2 * ni]     = w_w[n];
            wv[2 * ni + 1] = w_w[n + 1];
            dv[2 * ni]     = g_dec[b * HID_ + n];
            dv[2 * ni + 1] = g_dec[b * HID_ + n + 1];
        }
    }
    #pragma unroll
    for (int mi = 0; mi < 4; mi++) {
        #pragma unroll
        for (int h2 = 0; h2 < 2; h2++) {
            float p = 0.f;
            #pragma unroll
            for (int ni = 0; ni < 4; ni++) {
                #pragma unroll
                for (int j = 0; j < 2; j++) {
                    float s = acc[mi][ni][h2 * 2 + j] + dv[2 * ni + j];
                    p += wv[2 * ni + j] * tanhf(s);
                }
            }
            p += __shfl_xor_sync(0xffffffffu, p, 1);
            p += __shfl_xor_sync(0xffffffffu, p, 2);
            if ((lane & 3) == 0) {
                int row = mi * 16 + h2 * 8 + (lane >> 2);
                red[row * 8 + wn] = p;
            }
        }
    }
    __syncthreads();
    if (tid < TM) {
        float e = 0.f;
        #pragma unroll
        for (int w = 0; w < 8; w++) e += red[tid * 8 + w];
        g_energy[m0 + tid] = e;
    }
    #undef AHI
    #undef ALO
    #undef WHI
    #undef WLO
    #undef LOAD_W
    #undef STORE_A
}

// ---------------- masked softmax over T ----------------
__global__ void softmax_kernel(const int* __restrict__ text_len, float* __restrict__ out) {
    __shared__ float sh[T_];
    __shared__ float rbuf[256];
    int b = blockIdx.x, tid = threadIdx.x;
    int len = text_len[b];

    float mx = -INFINITY;
    for (int t = tid; t < T_; t += 256) {
        float v = (t < len) ? g_energy[b * T_ + t] : -INFINITY;
        sh[t] = v;
        mx = fmaxf(mx, v);
    }
    rbuf[tid] = mx; __syncthreads();
    for (int s = 128; s > 0; s >>= 1) {
        if (tid < s) rbuf[tid] = fmaxf(rbuf[tid], rbuf[tid + s]);
        __syncthreads();
    }
    mx = rbuf[0];
    __syncthreads();

    float sum = 0.f;
    for (int t = tid; t < T_; t += 256) {
        float v = sh[t];
        float e = (v == -INFINITY) ? 0.f : expf(v - mx);
        sh[t] = e;
        sum += e;
    }
    rbuf[tid] = sum; __syncthreads();
    for (int s = 128; s > 0; s >>= 1) {
        if (tid < s) rbuf[tid] += rbuf[tid + s];
        __syncthreads();
    }
    float inv = 1.f / rbuf[0];

    float* attw = out + B_ * ENC_;
    for (int t = tid; t < T_; t += 256)
        attw[b * T_ + t] = sh[t] * inv;
}

// ---------------- att_c = sum_t att_w[b,t] * enc[b,t,:]  (16 t-slices) ----------------
__global__ void attc_part(const float* __restrict__ enc, const float* __restrict__ attw) {
    __shared__ float w[128];
    int ts = blockIdx.x;    // 0..15
    int b  = blockIdx.y;
    int tid = threadIdx.x;  // 128
    w[tid] = attw[b * T_ + ts * 128 + tid];
    __syncthreads();

    const float4* e4 = (const float4*)(enc + ((size_t)b * T_ + ts * 128) * ENC_) + tid;
    float ax = 0.f, ay = 0.f, az = 0.f, aw = 0.f;
    #pragma unroll 8
    for (int tt = 0; tt < 128; tt++) {
        float4 v = e4[(size_t)tt * (ENC_ / 4)];
        float ww = w[tt];
        ax += ww * v.x; ay += ww * v.y; az += ww * v.z; aw += ww * v.w;
    }
    float4 r; r.x = ax; r.y = ay; r.z = az; r.w = aw;
    *(float4*)&g_part[((b * 16 + ts) * ENC_) + tid * 4] = r;
}

__global__ void attc_reduce(float* __restrict__ out) {
    int i = blockIdx.x * 256 + threadIdx.x;
    if (i < B_ * ENC_) {
        int b = i >> 9, c = i & (ENC_ - 1);
        float s = 0.f;
        #pragma unroll
        for (int ts = 0; ts < 16; ts++) s += g_part[(b * 16 + ts) * ENC_ + c];
        out[i] = s;
    }
}

// ---------------- launch ----------------
extern "C" void kernel_launch(void* const* d_in, const int* in_sizes, int n_in,
                              void* d_out, int out_size) {
    const float* enc       = (const float*)d_in[0];
    const float* dec_state = (const float*)d_in[1];
    const float* prev      = (const float*)d_in[2];
    const int*   text_len  = (const int*)d_in[3];
    const float* W_enc     = (const float*)d_in[4];
    const float* b_enc     = (const float*)d_in[5];
    const float* W_dec     = (const float*)d_in[6];
    const float* W_att     = (const float*)d_in[7];
    const float* conv_w    = (const float*)d_in[8];
    const float* w_w       = (const float*)d_in[9];
    // d_in[10] = w_b: additive constant cancels in softmax.
    float* out = (float*)d_out;

    cudaFuncSetAttribute(energy_kernel, cudaFuncAttributeMaxDynamicSharedMemorySize, SMEM2);

    prep_all<<<2592, 256>>>(W_enc, W_att, conv_w, dec_state, W_dec, b_enc);

    energy_kernel<<<(B_ * T_) / TM, 256, SMEM2>>>(enc, prev, w_w);

    softmax_kernel<<<B_, 256>>>(text_len, out);

    attc_part<<<dim3(16, B_), 128>>>(enc, out + B_ * ENC_);
    attc_reduce<<<(B_ * ENC_ + 255) / 256, 256>>>(out);
}

// round 5
// speedup vs baseline: 1.2427x; 1.2427x over previous
#include <cuda_runtime.h>
#include <cuda_bf16.h>
#include <math.h>
#include <stdint.h>

// Problem constants
#define B_    64
#define T_    2048
#define ENC_  512
#define DEC_  1024
#define HID_  256
#define KCONV 31
#define PADC  15

// Tiling: CTA = 128 (bt) x 256 (h), K-chunk 64, double-buffered smem
#define TM    128
#define KC    64
#define LDA   72                  // 64 + 8 pad bf16 (144B row, 16B aligned)
#define ROWB  144                 // bytes per row
// stage layout (bytes): Ahi[128*144) Alo Whi[256*144) Wlo
#define A_HI  0
#define A_LO  18432
#define W_HI  36864
#define W_LO  73728
#define STAGE_B 110592
#define SMEM_TOT (2 * STAGE_B)    // 221184

// ---------------- device scratch ----------------
__device__ __nv_bfloat16 g_Whi[HID_ * ENC_];
__device__ __nv_bfloat16 g_Wlo[HID_ * ENC_];
__device__ __nv_bfloat16 g_F[HID_ * 32];        // fused conv filter, col 31 = 0
__device__ float g_dec[B_ * HID_];              // dec projection + b_enc
__device__ float g_energy[B_ * T_];
__device__ float g_part[B_ * 16 * ENC_];        // att_c partials (16 t-slices)

// ---------------- PTX helpers ----------------
__device__ __forceinline__ void cp16(uint32_t dst, const void* src) {
    asm volatile("cp.async.cg.shared.global [%0], [%1], 16;\n" :: "r"(dst), "l"(src));
}
#define CP_COMMIT() asm volatile("cp.async.commit_group;\n" ::: "memory")
#define CP_WAIT0()  asm volatile("cp.async.wait_group 0;\n" ::: "memory")

__device__ __forceinline__ void ldsm_x4(uint32_t (&r)[4], uint32_t addr) {
    asm volatile("ldmatrix.sync.aligned.m8n8.x4.shared.b16 {%0,%1,%2,%3}, [%4];"
                 : "=r"(r[0]), "=r"(r[1]), "=r"(r[2]), "=r"(r[3]) : "r"(addr));
}

__device__ __forceinline__ void mma_bf16(float& c0, float& c1, float& c2, float& c3,
                                         uint32_t a0, uint32_t a1, uint32_t a2, uint32_t a3,
                                         uint32_t b0, uint32_t b1) {
    asm volatile(
        "mma.sync.aligned.m16n8k16.row.col.f32.bf16.bf16.f32 "
        "{%0,%1,%2,%3}, {%4,%5,%6,%7}, {%8,%9}, {%0,%1,%2,%3};"
        : "+f"(c0), "+f"(c1), "+f"(c2), "+f"(c3)
        : "r"(a0), "r"(a1), "r"(a2), "r"(a3), "r"(b0), "r"(b1));
}

// ---------------- merged prep kernel ----------------
__global__ void prep_all(const float* __restrict__ W_enc,
                         const float* __restrict__ W_att,
                         const float* __restrict__ conv_w,
                         const float* __restrict__ dec_state,
                         const float* __restrict__ W_dec,
                         const float* __restrict__ b_enc) {
    int bx = blockIdx.x, tid = threadIdx.x;
    if (bx < 512) {
        int i = bx * 256 + tid;
        float x = W_enc[i];
        __nv_bfloat16 h = __float2bfloat16(x);
        g_Whi[i] = h;
        g_Wlo[i] = __float2bfloat16(x - __bfloat162float(h));
    } else if (bx < 544) {
        int i = (bx - 512) * 256 + tid;
        int h = i >> 5, k = i & 31;
        float s = 0.f;
        if (k < KCONV) {
            #pragma unroll
            for (int c = 0; c < 32; c++) s += W_att[h * 32 + c] * conv_w[c * KCONV + k];
        }
        g_F[i] = __float2bfloat16(s);
    } else {
        int wid_g = (bx - 544) * 8 + (tid >> 5);
        int lane = tid & 31;
        int b = wid_g >> 8, h = wid_g & 255;
        const float4* d = (const float4*)(dec_state + (size_t)b * DEC_);
        const float4* w = (const float4*)(W_dec + (size_t)h * DEC_);
        float s = 0.f;
        #pragma unroll
        for (int it = 0; it < 8; it++) {
            float4 dv = d[lane + it * 32];
            float4 wv = w[lane + it * 32];
            s += dv.x * wv.x + dv.y * wv.y + dv.z * wv.z + dv.w * wv.w;
        }
        #pragma unroll
        for (int off = 16; off > 0; off >>= 1) s += __shfl_xor_sync(0xffffffffu, s, off);
        if (lane == 0) g_dec[wid_g] = s + b_enc[h];
    }
}

// ---------------- mma pass with ldmatrix ----------------
// As: u32 smem addr of [TM][LDA] bf16; Ws: u32 addr of [256][LDA] bf16.
// Warp (wm, wn): rows [wm*64, +64), cols [wn*64, +64).
__device__ __forceinline__ void mma_pass(uint32_t As, uint32_t Ws, int ksteps,
                                         float (&acc)[4][8][4],
                                         int wm, int wn, int lane) {
    // per-lane ldmatrix row addressing
    const int a_row = (lane & 7) + ((lane >> 3) & 1) * 8;
    const int a_col = ((lane >> 4) & 1) * 8;
    const int b_row = (lane & 7) + ((lane >> 4) & 1) * 8;
    const int b_col = ((lane >> 3) & 1) * 8;

    for (int ks = 0; ks < ksteps; ks++) {
        const int kb = ks * 16;
        uint32_t a[4][4];
        #pragma unroll
        for (int mi = 0; mi < 4; mi++) {
            uint32_t addr = As + (uint32_t)((wm * 64 + mi * 16 + a_row) * ROWB
                                            + (kb + a_col) * 2);
            ldsm_x4(a[mi], addr);
        }
        uint32_t bf[4][4];
        #pragma unroll
        for (int p = 0; p < 4; p++) {
            uint32_t addr = Ws + (uint32_t)((wn * 64 + p * 16 + b_row) * ROWB
                                            + (kb + b_col) * 2);
            ldsm_x4(bf[p], addr);
        }
        #pragma unroll
        for (int p = 0; p < 4; p++) {
            #pragma unroll
            for (int mi = 0; mi < 4; mi++) {
                mma_bf16(acc[mi][2*p][0], acc[mi][2*p][1], acc[mi][2*p][2], acc[mi][2*p][3],
                         a[mi][0], a[mi][1], a[mi][2], a[mi][3], bf[p][0], bf[p][1]);
                mma_bf16(acc[mi][2*p+1][0], acc[mi][2*p+1][1], acc[mi][2*p+1][2], acc[mi][2*p+1][3],
                         a[mi][0], a[mi][1], a[mi][2], a[mi][3], bf[p][2], bf[p][3]);
            }
        }
    }
}

// ---------------- energy kernel (pipelined mma.sync) ----------------
__global__ void __launch_bounds__(256)
energy_kernel(const float* __restrict__ enc,
              const float* __restrict__ prev,
              const float* __restrict__ w_w) {
    extern __shared__ char sm[];
    uint32_t smb;
    asm("{ .reg .u64 t; cvta.to.shared.u64 t, %1; cvt.u32.u64 %0, t; }"
        : "=r"(smb) : "l"(sm));

    const int tid  = threadIdx.x;
    const int lane = tid & 31;
    const int warp = tid >> 5;
    const int wm   = warp >> 2;    // 0..1
    const int wn   = warp & 3;     // 0..3

    const int m0 = blockIdx.x * TM;
    const int b  = m0 >> 11;
    const int t0 = m0 & (T_ - 1);

    const int r    = tid >> 1;     // A row this thread loads (0..127)
    const int half = tid & 1;      // 32-col half

    float acc[4][8][4];
    #pragma unroll
    for (int mi = 0; mi < 4; mi++)
        #pragma unroll
        for (int ni = 0; ni < 8; ni++)
            #pragma unroll
            for (int q = 0; q < 4; q++) acc[mi][ni][q] = 0.f;

    const float* arow = enc + ((size_t)b * T_ + t0 + r) * ENC_ + half * 32;

    // ---- helpers as lambdas ----
    auto load_w = [&](int s, int kc) {
        const __nv_bfloat16* wh = g_Whi + (size_t)tid * ENC_ + kc;
        const __nv_bfloat16* wl = g_Wlo + (size_t)tid * ENC_ + kc;
        uint32_t dh = smb + s * STAGE_B + W_HI + tid * ROWB;
        uint32_t dl = smb + s * STAGE_B + W_LO + tid * ROWB;
        #pragma unroll
        for (int j = 0; j < 8; j++) {
            cp16(dh + j * 16, wh + j * 8);
            cp16(dl + j * 16, wl + j * 8);
        }
    };
    float4 av[8];
    auto load_a = [&](int kc) {
        const float4* ap = (const float4*)(arow + kc);
        #pragma unroll
        for (int j = 0; j < 8; j++) av[j] = ap[j];
    };
    auto store_a = [&](int s) {
        char* dh = sm + s * STAGE_B + A_HI + r * ROWB + half * 64;
        char* dl = sm + s * STAGE_B + A_LO + r * ROWB + half * 64;
        #pragma unroll
        for (int j = 0; j < 4; j++) {
            float fv[8] = {av[2*j].x, av[2*j].y, av[2*j].z, av[2*j].w,
                           av[2*j+1].x, av[2*j+1].y, av[2*j+1].z, av[2*j+1].w};
            uint32_t hi[4], lo[4];
            #pragma unroll
            for (int q = 0; q < 4; q++) {
                __nv_bfloat16 h0 = __float2bfloat16(fv[2*q]);
                __nv_bfloat16 h1 = __float2bfloat16(fv[2*q+1]);
                __nv_bfloat162 hp; hp.x = h0; hp.y = h1;
                __nv_bfloat162 lp = __floats2bfloat162_rn(
                    fv[2*q]   - __bfloat162float(h0),
                    fv[2*q+1] - __bfloat162float(h1));
                hi[q] = *(uint32_t*)&hp;
                lo[q] = *(uint32_t*)&lp;
            }
            *(uint4*)(dh + j * 16) = make_uint4(hi[0], hi[1], hi[2], hi[3]);
            *(uint4*)(dl + j * 16) = make_uint4(lo[0], lo[1], lo[2], lo[3]);
        }
    };

    // ---- prologue: chunk 0 ----
    load_w(0, 0);
    CP_COMMIT();
    load_a(0);
    store_a(0);
    CP_WAIT0();
    __syncthreads();

    // ---- main loop: 8 chunks of KC=64 ----
    for (int c = 0; c < 8; c++) {
        const int cur = c & 1, nxt = cur ^ 1;
        const uint32_t stg = smb + cur * STAGE_B;
        if (c < 7) {
            load_w(nxt, (c + 1) * KC);
            CP_COMMIT();
            load_a((c + 1) * KC);
        }
        mma_pass(stg + A_HI, stg + W_HI, 4, acc, wm, wn, lane);  // hi*hi
        mma_pass(stg + A_LO, stg + W_HI, 4, acc, wm, wn, lane);  // lo*hi
        mma_pass(stg + A_HI, stg + W_LO, 4, acc, wm, wn, lane);  // hi*lo
        if (c < 7) {
            store_a(nxt);
            CP_WAIT0();
        }
        __syncthreads();
    }

    // ---- conv chunk: shifted prev (128x32) x F (256x32) into stage 0 ----
    {
        uint32_t dh = smb + W_HI + tid * ROWB;
        #pragma unroll
        for (int j = 0; j < 4; j++) cp16(dh + j * 16, g_F + tid * 32 + j * 8);
        CP_COMMIT();
        if (half == 0) {
            char* da = sm + A_HI + r * ROWB;
            #pragma unroll
            for (int j = 0; j < 4; j++) {
                uint32_t hw[4];
                #pragma unroll
                for (int q = 0; q < 4; q++) {
                    int k0 = j * 8 + q * 2;
                    int t1 = t0 + r - PADC + k0;
                    int t2 = t1 + 1;
                    float va = (k0 < KCONV && t1 >= 0 && t1 < T_) ? prev[b * T_ + t1] : 0.f;
                    float vb = (k0 + 1 < KCONV && t2 >= 0 && t2 < T_) ? prev[b * T_ + t2] : 0.f;
                    __nv_bfloat162 hp = __floats2bfloat162_rn(va, vb);
                    hw[q] = *(uint32_t*)&hp;
                }
                *(uint4*)(da + j * 16) = make_uint4(hw[0], hw[1], hw[2], hw[3]);
            }
        }
        CP_WAIT0();
        __syncthreads();
        mma_pass(smb + A_HI, smb + W_HI, 2, acc, wm, wn, lane);
        __syncthreads();
    }

    // ---- epilogue: energy[row] = sum_h w_w[h]*tanh(acc + dec) ----
    float* red = (float*)sm;   // 128 x 4 floats, aliases stage0 (post-sync)
    float wv[16], dv[16];
    {
        int cbase = wn * 64 + (lane & 3) * 2;
        #pragma unroll
        for (int ni = 0; ni < 8; ni++) {
            int n = cbase + ni * 8;
            wv[2 * ni]     = w_w[n];
            wv[2 * ni + 1] = w_w[n + 1];
            dv[2 * ni]     = g_dec[b * HID_ + n];
            dv[2 * ni + 1] = g_dec[b * HID_ + n + 1];
        }
    }
    #pragma unroll
    for (int mi = 0; mi < 4; mi++) {
        #pragma unroll
        for (int h2 = 0; h2 < 2; h2++) {
            float p = 0.f;
            #pragma unroll
            for (int ni = 0; ni < 8; ni++) {
                #pragma unroll
                for (int j = 0; j < 2; j++) {
                    float s = acc[mi][ni][h2 * 2 + j] + dv[2 * ni + j];
                    p += wv[2 * ni + j] * tanhf(s);
                }
            }
            p += __shfl_xor_sync(0xffffffffu, p, 1);
            p += __shfl_xor_sync(0xffffffffu, p, 2);
            if ((lane & 3) == 0) {
                int row = wm * 64 + mi * 16 + h2 * 8 + (lane >> 2);
                red[row * 4 + wn] = p;
            }
        }
    }
    __syncthreads();
    if (tid < TM) {
        float e = red[tid * 4] + red[tid * 4 + 1] + red[tid * 4 + 2] + red[tid * 4 + 3];
        g_energy[m0 + tid] = e;
    }
}

// ---------------- masked softmax over T ----------------
__global__ void softmax_kernel(const int* __restrict__ text_len, float* __restrict__ out) {
    __shared__ float sh[T_];
    __shared__ float rbuf[256];
    int b = blockIdx.x, tid = threadIdx.x;
    int len = text_len[b];

    float mx = -INFINITY;
    for (int t = tid; t < T_; t += 256) {
        float v = (t < len) ? g_energy[b * T_ + t] : -INFINITY;
        sh[t] = v;
        mx = fmaxf(mx, v);
    }
    rbuf[tid] = mx; __syncthreads();
    for (int s = 128; s > 0; s >>= 1) {
        if (tid < s) rbuf[tid] = fmaxf(rbuf[tid], rbuf[tid + s]);
        __syncthreads();
    }
    mx = rbuf[0];
    __syncthreads();

    float sum = 0.f;
    for (int t = tid; t < T_; t += 256) {
        float v = sh[t];
        float e = (v == -INFINITY) ? 0.f : expf(v - mx);
        sh[t] = e;
        sum += e;
    }
    rbuf[tid] = sum; __syncthreads();
    for (int s = 128; s > 0; s >>= 1) {
        if (tid < s) rbuf[tid] += rbuf[tid + s];
        __syncthreads();
    }
    float inv = 1.f / rbuf[0];

    float* attw = out + B_ * ENC_;
    for (int t = tid; t < T_; t += 256)
        attw[b * T_ + t] = sh[t] * inv;
}

// ---------------- att_c = sum_t att_w[b,t] * enc[b,t,:]  (16 t-slices) ----------------
__global__ void attc_part(const float* __restrict__ enc, const float* __restrict__ attw) {
    __shared__ float w[128];
    int ts = blockIdx.x;    // 0..15
    int b  = blockIdx.y;
    int tid = threadIdx.x;  // 128
    w[tid] = attw[b * T_ + ts * 128 + tid];
    __syncthreads();

    const float4* e4 = (const float4*)(enc + ((size_t)b * T_ + ts * 128) * ENC_) + tid;
    float ax = 0.f, ay = 0.f, az = 0.f, aw = 0.f;
    #pragma unroll 8
    for (int tt = 0; tt < 128; tt++) {
        float4 v = e4[(size_t)tt * (ENC_ / 4)];
        float ww = w[tt];
        ax += ww * v.x; ay += ww * v.y; az += ww * v.z; aw += ww * v.w;
    }
    float4 rr; rr.x = ax; rr.y = ay; rr.z = az; rr.w = aw;
    *(float4*)&g_part[((b * 16 + ts) * ENC_) + tid * 4] = rr;
}

__global__ void attc_reduce(float* __restrict__ out) {
    int i = blockIdx.x * 256 + threadIdx.x;
    if (i < B_ * ENC_) {
        int b = i >> 9, c = i & (ENC_ - 1);
        float s = 0.f;
        #pragma unroll
        for (int ts = 0; ts < 16; ts++) s += g_part[(b * 16 + ts) * ENC_ + c];
        out[i] = s;
    }
}

// ---------------- launch ----------------
extern "C" void kernel_launch(void* const* d_in, const int* in_sizes, int n_in,
                              void* d_out, int out_size) {
    const float* enc       = (const float*)d_in[0];
    const float* dec_state = (const float*)d_in[1];
    const float* prev      = (const float*)d_in[2];
    const int*   text_len  = (const int*)d_in[3];
    const float* W_enc     = (const float*)d_in[4];
    const float* b_enc     = (const float*)d_in[5];
    const float* W_dec     = (const float*)d_in[6];
    const float* W_att     = (const float*)d_in[7];
    const float* conv_w    = (const float*)d_in[8];
    const float* w_w       = (const float*)d_in[9];
    // d_in[10] = w_b: additive constant cancels in softmax.
    float* out = (float*)d_out;

    cudaFuncSetAttribute(energy_kernel, cudaFuncAttributeMaxDynamicSharedMemorySize, SMEM_TOT);

    prep_all<<<2592, 256>>>(W_enc, W_att, conv_w, dec_state, W_dec, b_enc);

    energy_kernel<<<(B_ * T_) / TM, 256, SMEM_TOT>>>(enc, prev, w_w);

    softmax_kernel<<<B_, 256>>>(text_len, out);

    attc_part<<<dim3(16, B_), 128>>>(enc, out + B_ * ENC_);
    attc_reduce<<<(B_ * ENC_ + 255) / 256, 256>>>(out);
}